// round 5
// baseline (speedup 1.0000x reference)
#include <cuda_runtime.h>
#include <cuda_bf16.h>
#include <cstdint>

#define T_STEPS 128
#define BATCH   512
#define NLAB    512
#define HID     1024
#define SEM     1024
#define MROWS   (T_STEPS*BATCH)    // 65536
#define FIXCAP  (1u<<20)
#define GUARD   1e-3f

// ---------------- scratch (device globals; no allocs allowed) ----------------
__device__ __nv_bfloat16 g_a1  [(size_t)MROWS * NLAB];   //  64 MB spikes bf16
__device__ __nv_bfloat16 g_spk1[(size_t)MROWS * HID];    // 128 MB layer-1 spikes bf16
__device__ float         g_I   [(size_t)MROWS * HID];    // 256 MB currents (reused)
__device__ __nv_bfloat16 g_ws1 [3ull * HID * NLAB];      //   3 MB W1 splits
__device__ __nv_bfloat16 g_ws2 [3ull * SEM * HID];       //   6 MB W2 splits
__device__ unsigned int  g_fixcnt;
__device__ unsigned int  g_fixlist[FIXCAP];

// ============================================================================
// HMMA 3-split GEMM: C[M,1024] = sum_sp A[M,K]_bf16 @ Wsp[1024,K]^T, fp32 out.
// Products exact (binary A, split W); only accumulation order differs.
// ============================================================================
#define BM2 128
#define BN2 128
#define BK2 32
#define STAGES 4
#define PADK  (BK2 + 8)
#define ROWB  (PADK * 2)               // 80 B/row
#define A_BYTES  (BM2 * ROWB)
#define B_SPLIT  (BN2 * ROWB)
#define STAGE_BYTES (A_BYTES + 3 * B_SPLIT)
#define SMEM_BYTES  (STAGES * STAGE_BYTES)   // 163840

__device__ __forceinline__ uint32_t s2u(const void* p) {
    uint32_t a;
    asm("{ .reg .u64 t; cvta.to.shared.u64 t, %1; cvt.u32.u64 %0, t; }" : "=r"(a) : "l"(p));
    return a;
}
__device__ __forceinline__ void cpa16(uint32_t dst, const void* src) {
    asm volatile("cp.async.cg.shared.global [%0], [%1], 16;" :: "r"(dst), "l"(src) : "memory");
}
__device__ __forceinline__ void ldsm_x4(uint32_t* r, uint32_t addr) {
    asm volatile("ldmatrix.sync.aligned.m8n8.x4.shared.b16 {%0,%1,%2,%3}, [%4];"
                 : "=r"(r[0]), "=r"(r[1]), "=r"(r[2]), "=r"(r[3]) : "r"(addr));
}
__device__ __forceinline__ void mma16816(float* c, const uint32_t* a, uint32_t b0, uint32_t b1) {
    asm volatile("mma.sync.aligned.m16n8k16.row.col.f32.bf16.bf16.f32 "
                 "{%0,%1,%2,%3}, {%4,%5,%6,%7}, {%8,%9}, {%0,%1,%2,%3};"
                 : "+f"(c[0]), "+f"(c[1]), "+f"(c[2]), "+f"(c[3])
                 : "r"(a[0]), "r"(a[1]), "r"(a[2]), "r"(a[3]), "r"(b0), "r"(b1));
}

template <int K>
__global__ void __launch_bounds__(256, 1)
gemm3s(const __nv_bfloat16* __restrict__ A,
       const __nv_bfloat16* __restrict__ W,    // [3][1024][K]
       float* __restrict__ C)
{
    extern __shared__ char smem[];
    const uint32_t sb = s2u(smem);
    const int tid = threadIdx.x;
    const size_t mBase = (size_t)blockIdx.y * BM2;
    const size_t nBase = (size_t)blockIdx.x * BN2;
    constexpr int NC = K / BK2;

    auto load_stage = [&](int chunk, int stage) {
        const uint32_t s0 = sb + stage * STAGE_BYTES;
        const int k0 = chunk * BK2;
#pragma unroll
        for (int j = 0; j < 2; ++j) {
            int c = tid * 2 + j;
            int row = c >> 2, kc = c & 3;
            cpa16(s0 + row * ROWB + kc * 16,
                  (const char*)(A + (mBase + row) * (size_t)K + k0) + kc * 16);
        }
#pragma unroll
        for (int j = 0; j < 6; ++j) {
            int c = tid + j * 256;
            int sp = c >> 9, rem = c & 511;
            int row = rem >> 2, kc = rem & 3;
            cpa16(s0 + A_BYTES + sp * B_SPLIT + row * ROWB + kc * 16,
                  (const char*)(W + sp * (size_t)1024 * K + (nBase + row) * (size_t)K + k0) + kc * 16);
        }
        asm volatile("cp.async.commit_group;" ::: "memory");
    };

    const int wid  = tid >> 5, lane = tid & 31;
    const int wm = (wid >> 1) * 32;
    const int wn = (wid & 1) * 64;

    float acc[2][8][4];
#pragma unroll
    for (int mi = 0; mi < 2; ++mi)
#pragma unroll
        for (int ni = 0; ni < 8; ++ni)
#pragma unroll
            for (int q = 0; q < 4; ++q) acc[mi][ni][q] = 0.f;

    for (int s = 0; s < STAGES - 1; ++s) load_stage(s, s);

    // ldmatrix lane-address components
    const uint32_t a_lrow = (uint32_t)(lane & 15);          // row within 16
    const uint32_t a_koff = (uint32_t)(lane >> 4) * 8;      // k half
    const uint32_t b_lrow = (uint32_t)(((lane >> 3) & 1) * 8 + (lane & 7));
    const uint32_t b_koff = (uint32_t)(lane >> 4) * 8;

    for (int i = 0; i < NC; ++i) {
        const int nxt = i + STAGES - 1;
        if (nxt < NC) load_stage(nxt, nxt & (STAGES - 1));
        else asm volatile("cp.async.commit_group;" ::: "memory");
        asm volatile("cp.async.wait_group %0;" :: "n"(STAGES - 2) : "memory");
        __syncthreads();

        const uint32_t s0 = sb + (i & (STAGES - 1)) * STAGE_BYTES;
#pragma unroll
        for (int ks = 0; ks < 2; ++ks) {
            const int k = ks * 16;
            uint32_t af[2][4];
#pragma unroll
            for (int mi = 0; mi < 2; ++mi)
                ldsm_x4(af[mi], s0 + (wm + mi * 16 + a_lrow) * ROWB + (k + a_koff) * 2);
#pragma unroll
            for (int sp = 0; sp < 3; ++sp) {
                const uint32_t bbase = s0 + A_BYTES + sp * B_SPLIT;
#pragma unroll
                for (int nb = 0; nb < 4; ++nb) {   // each x4 covers ni = 2nb, 2nb+1
                    uint32_t q[4];
                    ldsm_x4(q, bbase + (wn + nb * 16 + b_lrow) * ROWB + (k + b_koff) * 2);
                    mma16816(acc[0][2 * nb],     af[0], q[0], q[2]);
                    mma16816(acc[1][2 * nb],     af[1], q[0], q[2]);
                    mma16816(acc[0][2 * nb + 1], af[0], q[1], q[3]);
                    mma16816(acc[1][2 * nb + 1], af[1], q[1], q[3]);
                }
            }
        }
        __syncthreads();
    }

    const int r0 = lane >> 2, c0 = (lane & 3) * 2;
#pragma unroll
    for (int mi = 0; mi < 2; ++mi)
#pragma unroll
        for (int ni = 0; ni < 8; ++ni) {
            float* p = C + (mBase + wm + mi * 16 + r0) * 1024 + nBase + wn + ni * 8 + c0;
            *(float2*)p              = make_float2(acc[mi][ni][0], acc[mi][ni][1]);
            *(float2*)(p + 8 * 1024) = make_float2(acc[mi][ni][2], acc[mi][ni][3]);
        }
}

// ============================================================================
// LIF kernels
// ============================================================================
// Layer-1 LIF with guard band: flag any element whose v ever lands within
// GUARD of threshold (HMMA-vs-exact error << GUARD => unflagged == exact).
__global__ void __launch_bounds__(256)
lif1_guard(const float* __restrict__ I, __nv_bfloat16* __restrict__ spk,
           float* __restrict__ mean_out)
{
    const size_t idx    = (size_t)blockIdx.x * blockDim.x + threadIdx.x;
    const size_t stride = (size_t)BATCH * 1024;
    float v = 0.f, cnt = 0.f;
    int bad = 0;
#pragma unroll 8
    for (int t = 0; t < T_STEPS; t++) {
        float x = I[idx + (size_t)t * stride];
        v = fmaf(0.95f, v, x);
        bad |= (fabsf(v - 1.0f) < GUARD);
        float s = (v > 1.0f) ? 1.0f : 0.0f;
        v *= (1.0f - s);
        spk[idx + (size_t)t * stride] = __float2bfloat16(s);
        cnt += s;
    }
    mean_out[idx] = cnt * (1.0f / 128.0f);
    if (bad) {
        unsigned int pos = atomicAdd(&g_fixcnt, 1u);
        if (pos < FIXCAP) g_fixlist[pos] = (unsigned int)idx;
    }
}

// Exact recompute of flagged elements: ascending-k fp32 FMA chain (same op
// sequence as the R1/R4 exact path), full LIF trajectory, rewrite spk1+mean1.
__global__ void __launch_bounds__(128)
fix_kernel(const float* __restrict__ spikes,   // (T,B,512) fp32
           const float* __restrict__ W1,       // (1024,512) fp32
           __nv_bfloat16* __restrict__ spk,
           float* __restrict__ mean_out)
{
    const unsigned int nfix = min(g_fixcnt, FIXCAP);
    const int lane = threadIdx.x & 31;
    const int gw = (blockIdx.x * blockDim.x + threadIdx.x) >> 5;
    const int nw = (gridDim.x * blockDim.x) >> 5;

    for (unsigned int w = gw; w < nfix; w += nw) {
        const unsigned int idx = g_fixlist[w];
        const int b = idx >> 10, u = idx & 1023;
        const float4* wr = (const float4*)(W1 + (size_t)u * NLAB);

        float Iv[4];
#pragma unroll
        for (int slot = 0; slot < 4; ++slot) {
            const int t = slot * 32 + lane;
            const float4* xr = (const float4*)(spikes + ((size_t)t * BATCH + b) * NLAB);
            float a = 0.f;
            for (int kk = 0; kk < NLAB / 4; ++kk) {
                float4 x = xr[kk], ww = wr[kk];
                a = fmaf(x.x, ww.x, a);
                a = fmaf(x.y, ww.y, a);
                a = fmaf(x.z, ww.z, a);
                a = fmaf(x.w, ww.w, a);
            }
            Iv[slot] = a;
        }
        float v = 0.f, cnt = 0.f;
        for (int t = 0; t < T_STEPS; ++t) {
            float x = __shfl_sync(0xffffffffu, Iv[t >> 5], t & 31);
            v = fmaf(0.95f, v, x);
            float s = (v > 1.0f) ? 1.0f : 0.0f;
            v *= (1.0f - s);
            cnt += s;
            if (lane == 0)
                spk[idx + (size_t)t * BATCH * 1024] = __float2bfloat16(s);
        }
        if (lane == 0) mean_out[idx] = cnt * (1.0f / 128.0f);
    }
}

__global__ void __launch_bounds__(256)
lif2_kernel(const float* __restrict__ I, float* __restrict__ mean_out)
{
    const size_t idx    = (size_t)blockIdx.x * blockDim.x + threadIdx.x;
    const size_t stride = (size_t)BATCH * 1024;
    float v = 0.f, cnt = 0.f;
#pragma unroll 8
    for (int t = 0; t < T_STEPS; t++) {
        float x = I[idx + (size_t)t * stride];
        v = fmaf(0.95f, v, x);
        float s = (v > 1.0f) ? 1.0f : 0.0f;
        v *= (1.0f - s);
        cnt += s;
    }
    mean_out[idx] = cnt * (1.0f / 128.0f);
}

// ============================================================================
// prep kernels
// ============================================================================
__global__ void zero_cnt_kernel() { if (threadIdx.x == 0) g_fixcnt = 0; }

__global__ void __launch_bounds__(256)
f2bf_kernel(const float* __restrict__ x, __nv_bfloat16* __restrict__ y)
{
    size_t i = ((size_t)blockIdx.x * blockDim.x + threadIdx.x) * 4;
    float4 v = *(const float4*)(x + i);
    __nv_bfloat162 a; a.x = __float2bfloat16(v.x); a.y = __float2bfloat16(v.y);
    __nv_bfloat162 b; b.x = __float2bfloat16(v.z); b.y = __float2bfloat16(v.w);
    *(__nv_bfloat162*)(y + i)     = a;
    *(__nv_bfloat162*)(y + i + 2) = b;
}

// 3-way bf16 split: w == hi + mid + lo exactly (8+8+8 mantissa bits)
__global__ void __launch_bounds__(256)
wsplit_kernel(const float* __restrict__ w, __nv_bfloat16* __restrict__ o, int n)
{
    int i = blockIdx.x * blockDim.x + threadIdx.x;
    if (i >= n) return;
    float x = w[i];
    __nv_bfloat16 h = __float2bfloat16(x);
    float r1 = x - __bfloat162float(h);
    __nv_bfloat16 m = __float2bfloat16(r1);
    float r2 = r1 - __bfloat162float(m);
    __nv_bfloat16 l = __float2bfloat16(r2);
    o[i] = h; o[n + i] = m; o[2 * n + i] = l;
}

// ---------------------------------------------------------------------------
extern "C" void kernel_launch(void* const* d_in, const int* in_sizes, int n_in,
                              void* d_out, int out_size)
{
    const float* spikes = (const float*)d_in[0];   // (T, B, NLAB) fp32
    const float* W1     = (const float*)d_in[1];   // (HID, NLAB)
    const float* W2     = (const float*)d_in[2];   // (SEM, HID)
    float* out = (float*)d_out;                    // [mean1 | mean2]

    __nv_bfloat16 *a1, *spk1, *ws1, *ws2;
    float* Ibuf;
    cudaGetSymbolAddress((void**)&a1,   g_a1);
    cudaGetSymbolAddress((void**)&spk1, g_spk1);
    cudaGetSymbolAddress((void**)&Ibuf, g_I);
    cudaGetSymbolAddress((void**)&ws1,  g_ws1);
    cudaGetSymbolAddress((void**)&ws2,  g_ws2);

    cudaFuncSetAttribute(gemm3s<512>,  cudaFuncAttributeMaxDynamicSharedMemorySize, SMEM_BYTES);
    cudaFuncSetAttribute(gemm3s<1024>, cudaFuncAttributeMaxDynamicSharedMemorySize, SMEM_BYTES);

    // prep
    zero_cnt_kernel<<<1, 32>>>();
    f2bf_kernel<<<((size_t)MROWS * NLAB) / 1024, 256>>>(spikes, a1);
    wsplit_kernel<<<(HID * NLAB) / 256, 256>>>(W1, ws1, HID * NLAB);
    wsplit_kernel<<<(SEM * HID) / 256, 256>>>(W2, ws2, SEM * HID);

    // layer 1: HMMA + guarded LIF + exact fixup of borderline elements
    gemm3s<512><<<dim3(HID / BN2, MROWS / BM2), 256, SMEM_BYTES>>>(a1, ws1, Ibuf);
    lif1_guard<<<(BATCH * HID) / 256, 256>>>(Ibuf, spk1, out);
    fix_kernel<<<1024, 128>>>(spikes, W1, spk1, out);

    // layer 2: HMMA 3-split (zero flips with exact spk1, per R4)
    gemm3s<1024><<<dim3(SEM / BN2, MROWS / BM2), 256, SMEM_BYTES>>>(spk1, ws2, Ibuf);
    lif2_kernel<<<(BATCH * SEM) / 256, 256>>>(Ibuf, out + (size_t)BATCH * HID);
}

// round 7
// speedup vs baseline: 1.5307x; 1.5307x over previous
#include <cuda_runtime.h>
#include <cuda_bf16.h>
#include <cstdint>

#define T_STEPS 128
#define BATCH   512
#define NLAB    512
#define HID     1024
#define SEM     1024
#define MROWS   (T_STEPS*BATCH)    // 65536
#define FIXCAP  (1u<<20)
#define GUARD   1e-4f

typedef unsigned long long ull;

// ---------------- scratch (device globals; no allocs allowed) ----------------
// M index is b*128 + t (batch-major): one 128-row GEMM tile = full time
// trajectory of one batch row -> LIF fuses into the epilogue.
__device__ __nv_bfloat16 g_a1  [(size_t)MROWS * NLAB];   //  64 MB spikes bf16 (b,t)-major
__device__ __nv_bfloat16 g_spk1[(size_t)MROWS * HID];    // 128 MB layer-1 spikes bf16
__device__ __nv_bfloat16 g_ws1 [3ull * HID * NLAB];      //   3 MB W1 splits
__device__ __nv_bfloat16 g_ws2 [3ull * SEM * HID];       //   6 MB W2 splits
__device__ unsigned int  g_fixcnt;
__device__ unsigned int  g_fixlist[FIXCAP];

// ============================================================================
// HMMA 3-split GEMM with fused LIF epilogue.
// ============================================================================
#define BM2 128
#define BN2 128
#define BK2 32
#define STAGES 4
#define PADK  (BK2 + 8)
#define ROWB  (PADK * 2)               // 80 B/row
#define A_BYTES  (BM2 * ROWB)
#define B_SPLIT  (BN2 * ROWB)
#define STAGE_BYTES (A_BYTES + 3 * B_SPLIT)
#define SMEM_BYTES  (STAGES * STAGE_BYTES)   // 163840 (>= LIF staging 66048)
#define PITCH 129

__device__ __forceinline__ uint32_t s2u(const void* p) {
    uint32_t a;
    asm("{ .reg .u64 t; cvta.to.shared.u64 t, %1; cvt.u32.u64 %0, t; }" : "=r"(a) : "l"(p));
    return a;
}
__device__ __forceinline__ void cpa16(uint32_t dst, const void* src) {
    asm volatile("cp.async.cg.shared.global [%0], [%1], 16;" :: "r"(dst), "l"(src) : "memory");
}
__device__ __forceinline__ void ldsm_x4(uint32_t* r, uint32_t addr) {
    asm volatile("ldmatrix.sync.aligned.m8n8.x4.shared.b16 {%0,%1,%2,%3}, [%4];"
                 : "=r"(r[0]), "=r"(r[1]), "=r"(r[2]), "=r"(r[3]) : "r"(addr));
}
__device__ __forceinline__ void mma16816(float* c, const uint32_t* a, uint32_t b0, uint32_t b1) {
    asm volatile("mma.sync.aligned.m16n8k16.row.col.f32.bf16.bf16.f32 "
                 "{%0,%1,%2,%3}, {%4,%5,%6,%7}, {%8,%9}, {%0,%1,%2,%3};"
                 : "+f"(c[0]), "+f"(c[1]), "+f"(c[2]), "+f"(c[3])
                 : "r"(a[0]), "r"(a[1]), "r"(a[2]), "r"(a[3]), "r"(b0), "r"(b1));
}

// A rows are (b*128+t); blockIdx.y = b. Epilogue: acc -> smem [u][t] -> LIF.
// LAYER1: write bf16 spikes + guard-flag borderline elements. Else mean only.
template <int K, bool LAYER1>
__global__ void __launch_bounds__(256, 1)
gemm_lif(const __nv_bfloat16* __restrict__ A,
         const __nv_bfloat16* __restrict__ W,    // [3][1024][K]
         __nv_bfloat16* __restrict__ spk,        // layer1 only
         float* __restrict__ mean_out)
{
    extern __shared__ char smem[];
    const uint32_t sb = s2u(smem);
    const int tid = threadIdx.x;
    const int b = blockIdx.y;
    const size_t mBase = (size_t)b * BM2;
    const size_t nBase = (size_t)blockIdx.x * BN2;
    constexpr int NC = K / BK2;

    auto load_stage = [&](int chunk, int stage) {
        const uint32_t s0 = sb + stage * STAGE_BYTES;
        const int k0 = chunk * BK2;
#pragma unroll
        for (int j = 0; j < 2; ++j) {
            int c = tid * 2 + j;
            int row = c >> 2, kc = c & 3;
            cpa16(s0 + row * ROWB + kc * 16,
                  (const char*)(A + (mBase + row) * (size_t)K + k0) + kc * 16);
        }
#pragma unroll
        for (int j = 0; j < 6; ++j) {
            int c = tid + j * 256;
            int sp = c >> 9, rem = c & 511;
            int row = rem >> 2, kc = rem & 3;
            cpa16(s0 + A_BYTES + sp * B_SPLIT + row * ROWB + kc * 16,
                  (const char*)(W + sp * (size_t)1024 * K + (nBase + row) * (size_t)K + k0) + kc * 16);
        }
        asm volatile("cp.async.commit_group;" ::: "memory");
    };

    const int wid  = tid >> 5, lane = tid & 31;
    const int wm = (wid >> 1) * 32;
    const int wn = (wid & 1) * 64;

    float acc[2][8][4];
#pragma unroll
    for (int mi = 0; mi < 2; ++mi)
#pragma unroll
        for (int ni = 0; ni < 8; ++ni)
#pragma unroll
            for (int q = 0; q < 4; ++q) acc[mi][ni][q] = 0.f;

    load_stage(0, 0); load_stage(1, 1); load_stage(2, 2);

    const uint32_t a_lrow = (uint32_t)(lane & 15);
    const uint32_t a_koff = (uint32_t)(lane >> 4) * 8;
    const uint32_t b_lrow = (uint32_t)(((lane >> 3) & 1) * 8 + (lane & 7));
    const uint32_t b_koff = (uint32_t)(lane >> 4) * 8;

    for (int i = 0; i < NC; ++i) {
        asm volatile("cp.async.wait_group %0;" :: "n"(STAGES - 2) : "memory");
        __syncthreads();
        const int nxt = i + STAGES - 1;
        if (nxt < NC) load_stage(nxt, nxt & (STAGES - 1));
        else asm volatile("cp.async.commit_group;" ::: "memory");

        const uint32_t s0 = sb + (i & (STAGES - 1)) * STAGE_BYTES;
#pragma unroll
        for (int ks = 0; ks < 2; ++ks) {
            const int k = ks * 16;
            uint32_t af[2][4];
#pragma unroll
            for (int mi = 0; mi < 2; ++mi)
                ldsm_x4(af[mi], s0 + (wm + mi * 16 + a_lrow) * ROWB + (k + a_koff) * 2);
#pragma unroll
            for (int sp = 0; sp < 3; ++sp) {
                const uint32_t bbase = s0 + A_BYTES + sp * B_SPLIT;
#pragma unroll
                for (int nb = 0; nb < 4; ++nb) {
                    uint32_t q[4];
                    ldsm_x4(q, bbase + (wn + nb * 16 + b_lrow) * ROWB + (k + b_koff) * 2);
                    mma16816(acc[0][2 * nb],     af[0], q[0], q[2]);
                    mma16816(acc[1][2 * nb],     af[1], q[0], q[2]);
                    mma16816(acc[0][2 * nb + 1], af[0], q[1], q[3]);
                    mma16816(acc[1][2 * nb + 1], af[1], q[1], q[3]);
                }
            }
        }
    }

    // ---- fused LIF epilogue ----
    __syncthreads();                    // all compute + loads done; reuse smem
    float* sf = (float*)smem;           // [u][t], pitch PITCH (conflict-free)
    const int r0 = lane >> 2, c0 = (lane & 3) * 2;
#pragma unroll
    for (int mi = 0; mi < 2; ++mi)
#pragma unroll
        for (int ni = 0; ni < 8; ++ni) {
            const int t0 = wm + mi * 16 + r0;
            const int u0 = wn + ni * 8 + c0;
            sf[(u0    ) * PITCH + t0    ] = acc[mi][ni][0];
            sf[(u0 + 1) * PITCH + t0    ] = acc[mi][ni][1];
            sf[(u0    ) * PITCH + t0 + 8] = acc[mi][ni][2];
            sf[(u0 + 1) * PITCH + t0 + 8] = acc[mi][ni][3];
        }
    __syncthreads();

    if (tid < 128) {
        const int u = tid;
        const size_t uglob = nBase + u;
        float v = 0.f, cnt = 0.f;
        int bad = 0;
#pragma unroll 8
        for (int t = 0; t < T_STEPS; ++t) {
            float x = sf[u * PITCH + t];
            v = fmaf(0.95f, v, x);
            if (LAYER1) bad |= (fabsf(v - 1.0f) < GUARD);
            float s = (v > 1.0f) ? 1.0f : 0.0f;
            v *= (1.0f - s);
            cnt += s;
            if (LAYER1)
                spk[(mBase + t) * 1024 + uglob] = __float2bfloat16(s);
        }
        mean_out[(size_t)b * 1024 + uglob] = cnt * (1.0f / 128.0f);
        if (LAYER1 && bad) {
            unsigned int pos = atomicAdd(&g_fixcnt, 1u);
            if (pos < FIXCAP) g_fixlist[pos] = (unsigned int)(b * 1024 + uglob);
        }
    }
}

// ============================================================================
// Exact recompute of flagged layer-1 elements. One warp per element; lane
// owns timestep t = slot*32+lane, computes I via a PRIVATE ASCENDING-k fp32
// FMA chain (bit-compatible with the R1/R5-validated exact path). Vector
// loads; scalar-ordered FMAs. LIF sequenced by shuffle.
// ============================================================================
__global__ void __launch_bounds__(128)
fix_kernel(const __nv_bfloat16* __restrict__ a1,   // (b*128+t, 512) bf16
           const float* __restrict__ W1,           // (1024, 512) fp32
           __nv_bfloat16* __restrict__ spk,
           float* __restrict__ mean_out)
{
    const unsigned int nfix = min(g_fixcnt, FIXCAP);
    const int lane = threadIdx.x & 31;
    const int gw = (blockIdx.x * blockDim.x + threadIdx.x) >> 5;
    const int nw = (gridDim.x * blockDim.x) >> 5;

    for (unsigned int w = gw; w < nfix; w += nw) {
        const unsigned int idx = g_fixlist[w];
        const int b = idx >> 10, u = idx & 1023;
        const float* wr = W1 + (size_t)u * NLAB;   // lane-uniform -> broadcast

        float Iv[4];
#pragma unroll
        for (int slot = 0; slot < 4; ++slot) {
            const int t = slot * 32 + lane;
            const __nv_bfloat16* xr = a1 + ((size_t)b * T_STEPS + t) * NLAB;
            float a = 0.f;
            for (int kk = 0; kk < NLAB; kk += 8) {      // ascending k, in order
                uint4 raw = *(const uint4*)(xr + kk);   // 8 bf16
                float4 w0 = *(const float4*)(wr + kk);
                float4 w1 = *(const float4*)(wr + kk + 4);
                const __nv_bfloat162* px = (const __nv_bfloat162*)&raw;
                a = fmaf(__bfloat162float(px[0].x), w0.x, a);
                a = fmaf(__bfloat162float(px[0].y), w0.y, a);
                a = fmaf(__bfloat162float(px[1].x), w0.z, a);
                a = fmaf(__bfloat162float(px[1].y), w0.w, a);
                a = fmaf(__bfloat162float(px[2].x), w1.x, a);
                a = fmaf(__bfloat162float(px[2].y), w1.y, a);
                a = fmaf(__bfloat162float(px[3].x), w1.z, a);
                a = fmaf(__bfloat162float(px[3].y), w1.w, a);
            }
            Iv[slot] = a;
        }
        float v = 0.f, cnt = 0.f;
        for (int t = 0; t < T_STEPS; ++t) {
            float x = __shfl_sync(0xffffffffu, Iv[t >> 5], t & 31);
            v = fmaf(0.95f, v, x);
            float s = (v > 1.0f) ? 1.0f : 0.0f;
            v *= (1.0f - s);
            cnt += s;
            if (lane == 0)
                spk[((size_t)b * T_STEPS + t) * 1024 + u] = __float2bfloat16(s);
        }
        if (lane == 0) mean_out[idx] = cnt * (1.0f / 128.0f);
    }
}

// ============================================================================
// prep kernels
// ============================================================================
__global__ void zero_cnt_kernel() { if (threadIdx.x == 0) g_fixcnt = 0; }

// transpose (t,b) -> (b,t) rows while converting fp32 -> bf16 (binary: exact)
__global__ void __launch_bounds__(128)
f2bf_t_kernel(const float* __restrict__ x, __nv_bfloat16* __restrict__ y)
{
    const int row = blockIdx.x;            // t*BATCH + b
    const int t = row >> 9, b = row & 511;
    const float4* src = (const float4*)(x + (size_t)row * NLAB);
    __nv_bfloat16* dst = y + ((size_t)b * T_STEPS + t) * NLAB;
    float4 v = src[threadIdx.x];
    __nv_bfloat162 a; a.x = __float2bfloat16(v.x); a.y = __float2bfloat16(v.y);
    __nv_bfloat162 c; c.x = __float2bfloat16(v.z); c.y = __float2bfloat16(v.w);
    *(__nv_bfloat162*)(dst + threadIdx.x * 4)     = a;
    *(__nv_bfloat162*)(dst + threadIdx.x * 4 + 2) = c;
}

// 3-way bf16 split: w == hi + mid + lo exactly (8+8+8 mantissa bits)
__global__ void __launch_bounds__(256)
wsplit_kernel(const float* __restrict__ w, __nv_bfloat16* __restrict__ o, int n)
{
    int i = blockIdx.x * blockDim.x + threadIdx.x;
    if (i >= n) return;
    float x = w[i];
    __nv_bfloat16 h = __float2bfloat16(x);
    float r1 = x - __bfloat162float(h);
    __nv_bfloat16 m = __float2bfloat16(r1);
    float r2 = r1 - __bfloat162float(m);
    __nv_bfloat16 l = __float2bfloat16(r2);
    o[i] = h; o[n + i] = m; o[2 * n + i] = l;
}

// ---------------------------------------------------------------------------
extern "C" void kernel_launch(void* const* d_in, const int* in_sizes, int n_in,
                              void* d_out, int out_size)
{
    const float* spikes = (const float*)d_in[0];   // (T, B, NLAB) fp32
    const float* W1     = (const float*)d_in[1];   // (HID, NLAB)
    const float* W2     = (const float*)d_in[2];   // (SEM, HID)
    float* out = (float*)d_out;                    // [mean1 | mean2]

    __nv_bfloat16 *a1, *spk1, *ws1, *ws2;
    cudaGetSymbolAddress((void**)&a1,   g_a1);
    cudaGetSymbolAddress((void**)&spk1, g_spk1);
    cudaGetSymbolAddress((void**)&ws1,  g_ws1);
    cudaGetSymbolAddress((void**)&ws2,  g_ws2);

    cudaFuncSetAttribute((const void*)gemm_lif<512, true>,
                         cudaFuncAttributeMaxDynamicSharedMemorySize, SMEM_BYTES);
    cudaFuncSetAttribute((const void*)gemm_lif<1024, false>,
                         cudaFuncAttributeMaxDynamicSharedMemorySize, SMEM_BYTES);

    // prep
    zero_cnt_kernel<<<1, 32>>>();
    f2bf_t_kernel<<<MROWS, 128>>>(spikes, a1);
    wsplit_kernel<<<(HID * NLAB) / 256, 256>>>(W1, ws1, HID * NLAB);
    wsplit_kernel<<<(SEM * HID) / 256, 256>>>(W2, ws2, SEM * HID);

    // layer 1: HMMA + fused guarded LIF, then exact-order fixup
    gemm_lif<512, true><<<dim3(HID / BN2, BATCH), 256, SMEM_BYTES>>>(
        a1, ws1, spk1, out);
    fix_kernel<<<1024, 128>>>(a1, W1, spk1, out);

    // layer 2: HMMA + fused LIF (mean only)
    gemm_lif<1024, false><<<dim3(SEM / BN2, BATCH), 256, SMEM_BYTES>>>(
        spk1, ws2, nullptr, out + (size_t)BATCH * HID);
}

// round 8
// speedup vs baseline: 1.8467x; 1.2065x over previous
#include <cuda_runtime.h>
#include <cuda_bf16.h>
#include <cstdint>

#define T_STEPS 128
#define BATCH   512
#define NLAB    512
#define HID     1024
#define SEM     1024
#define MROWS   (T_STEPS*BATCH)    // 65536
#define FIXCAP  (1u<<20)
#define GUARD   1e-4f

typedef unsigned long long ull;

// ---------------- scratch (device globals; no allocs allowed) ----------------
// M index is b*128 + t (batch-major): one 128-row GEMM tile = full time
// trajectory of one batch row -> LIF fuses into the epilogue.
__device__ __nv_bfloat16 g_a1  [(size_t)MROWS * NLAB];   //  64 MB spikes bf16 (b,t)-major
__device__ __nv_bfloat16 g_spk1[(size_t)MROWS * HID];    // 128 MB layer-1 spikes bf16
__device__ __nv_bfloat16 g_ws1 [2ull * HID * NLAB];      //   2 MB W1 2-splits
__device__ __nv_bfloat16 g_ws2 [2ull * SEM * HID];       //   4 MB W2 2-splits
__device__ unsigned int  g_fixcnt1, g_fixcnt2;
__device__ unsigned int  g_fixlist1[FIXCAP];
__device__ unsigned int  g_fixlist2[FIXCAP];

// ============================================================================
// HMMA 2-split GEMM with fused guarded LIF epilogue.
// ============================================================================
#define BM2 128
#define BN2 128
#define BK2 32
#define STAGES 6
#define PADK  (BK2 + 8)
#define ROWB  (PADK * 2)               // 80 B/row
#define A_BYTES  (BM2 * ROWB)          // 10240
#define B_SPLIT  (BN2 * ROWB)          // 10240
#define STAGE_BYTES (A_BYTES + 2 * B_SPLIT)   // 30720
#define SMEM_BYTES  (STAGES * STAGE_BYTES)    // 184320 (>= LIF staging 66048)
#define PITCH 129

__device__ __forceinline__ uint32_t s2u(const void* p) {
    uint32_t a;
    asm("{ .reg .u64 t; cvta.to.shared.u64 t, %1; cvt.u32.u64 %0, t; }" : "=r"(a) : "l"(p));
    return a;
}
__device__ __forceinline__ void cpa16(uint32_t dst, const void* src) {
    asm volatile("cp.async.cg.shared.global [%0], [%1], 16;" :: "r"(dst), "l"(src) : "memory");
}
__device__ __forceinline__ void ldsm_x4(uint32_t* r, uint32_t addr) {
    asm volatile("ldmatrix.sync.aligned.m8n8.x4.shared.b16 {%0,%1,%2,%3}, [%4];"
                 : "=r"(r[0]), "=r"(r[1]), "=r"(r[2]), "=r"(r[3]) : "r"(addr));
}
__device__ __forceinline__ void mma16816(float* c, const uint32_t* a, uint32_t b0, uint32_t b1) {
    asm volatile("mma.sync.aligned.m16n8k16.row.col.f32.bf16.bf16.f32 "
                 "{%0,%1,%2,%3}, {%4,%5,%6,%7}, {%8,%9}, {%0,%1,%2,%3};"
                 : "+f"(c[0]), "+f"(c[1]), "+f"(c[2]), "+f"(c[3])
                 : "r"(a[0]), "r"(a[1]), "r"(a[2]), "r"(a[3]), "r"(b0), "r"(b1));
}

// A rows are (b*128+t); blockIdx.y = b. Epilogue: acc -> smem [u][t] -> LIF.
// Both layers guard-flag borderline elements; WRITE_SPK also emits bf16 spikes.
template <int K, bool WRITE_SPK>
__global__ void __launch_bounds__(256, 1)
gemm_lif(const __nv_bfloat16* __restrict__ A,
         const __nv_bfloat16* __restrict__ W,    // [2][1024][K]
         __nv_bfloat16* __restrict__ spk,        // WRITE_SPK only
         float* __restrict__ mean_out,
         unsigned int* __restrict__ fixcnt,
         unsigned int* __restrict__ fixlist)
{
    extern __shared__ char smem[];
    const uint32_t sb = s2u(smem);
    const int tid = threadIdx.x;
    const int b = blockIdx.y;
    const size_t mBase = (size_t)b * BM2;
    const size_t nBase = (size_t)blockIdx.x * BN2;
    constexpr int NC = K / BK2;

    auto load_stage = [&](int chunk, int stage) {
        const uint32_t s0 = sb + stage * STAGE_BYTES;
        const int k0 = chunk * BK2;
        // A: 128 rows x 4 chunks = 512 chunks, 2 per thread
#pragma unroll
        for (int j = 0; j < 2; ++j) {
            int c = tid * 2 + j;
            int row = c >> 2, kc = c & 3;
            cpa16(s0 + row * ROWB + kc * 16,
                  (const char*)(A + (mBase + row) * (size_t)K + k0) + kc * 16);
        }
        // B: 2 splits x 128 rows x 4 chunks = 1024 chunks, 4 per thread
#pragma unroll
        for (int j = 0; j < 4; ++j) {
            int c = tid + j * 256;
            int sp = c >> 9, rem = c & 511;
            int row = rem >> 2, kc = rem & 3;
            cpa16(s0 + A_BYTES + sp * B_SPLIT + row * ROWB + kc * 16,
                  (const char*)(W + sp * (size_t)1024 * K + (nBase + row) * (size_t)K + k0) + kc * 16);
        }
        asm volatile("cp.async.commit_group;" ::: "memory");
    };

    const int wid  = tid >> 5, lane = tid & 31;
    const int wm = (wid >> 1) * 32;
    const int wn = (wid & 1) * 64;

    float acc[2][8][4];
#pragma unroll
    for (int mi = 0; mi < 2; ++mi)
#pragma unroll
        for (int ni = 0; ni < 8; ++ni)
#pragma unroll
            for (int q = 0; q < 4; ++q) acc[mi][ni][q] = 0.f;

#pragma unroll
    for (int s = 0; s < STAGES - 1; ++s) load_stage(s, s);

    const uint32_t a_lrow = (uint32_t)(lane & 15);
    const uint32_t a_koff = (uint32_t)(lane >> 4) * 8;
    const uint32_t b_lrow = (uint32_t)(((lane >> 3) & 1) * 8 + (lane & 7));
    const uint32_t b_koff = (uint32_t)(lane >> 4) * 8;

    int st = 0, nst = STAGES - 1;
    for (int i = 0; i < NC; ++i) {
        asm volatile("cp.async.wait_group %0;" :: "n"(STAGES - 2) : "memory");
        __syncthreads();
        const int nxt = i + STAGES - 1;
        if (nxt < NC) load_stage(nxt, nst);
        else asm volatile("cp.async.commit_group;" ::: "memory");
        if (++nst == STAGES) nst = 0;

        const uint32_t s0 = sb + st * STAGE_BYTES;
        if (++st == STAGES) st = 0;
#pragma unroll
        for (int ks = 0; ks < 2; ++ks) {
            const int k = ks * 16;
            uint32_t af[2][4];
#pragma unroll
            for (int mi = 0; mi < 2; ++mi)
                ldsm_x4(af[mi], s0 + (wm + mi * 16 + a_lrow) * ROWB + (k + a_koff) * 2);
#pragma unroll
            for (int sp = 0; sp < 2; ++sp) {
                const uint32_t bbase = s0 + A_BYTES + sp * B_SPLIT;
#pragma unroll
                for (int nb = 0; nb < 4; ++nb) {
                    uint32_t q[4];
                    ldsm_x4(q, bbase + (wn + nb * 16 + b_lrow) * ROWB + (k + b_koff) * 2);
                    mma16816(acc[0][2 * nb],     af[0], q[0], q[2]);
                    mma16816(acc[1][2 * nb],     af[1], q[0], q[2]);
                    mma16816(acc[0][2 * nb + 1], af[0], q[1], q[3]);
                    mma16816(acc[1][2 * nb + 1], af[1], q[1], q[3]);
                }
            }
        }
    }

    // ---- fused guarded LIF epilogue ----
    __syncthreads();                    // all compute + loads done; reuse smem
    float* sf = (float*)smem;           // [u][t], pitch PITCH (conflict-free)
    const int r0 = lane >> 2, c0 = (lane & 3) * 2;
#pragma unroll
    for (int mi = 0; mi < 2; ++mi)
#pragma unroll
        for (int ni = 0; ni < 8; ++ni) {
            const int t0 = wm + mi * 16 + r0;
            const int u0 = wn + ni * 8 + c0;
            sf[(u0    ) * PITCH + t0    ] = acc[mi][ni][0];
            sf[(u0 + 1) * PITCH + t0    ] = acc[mi][ni][1];
            sf[(u0    ) * PITCH + t0 + 8] = acc[mi][ni][2];
            sf[(u0 + 1) * PITCH + t0 + 8] = acc[mi][ni][3];
        }
    __syncthreads();

    if (tid < 128) {
        const int u = tid;
        const size_t uglob = nBase + u;
        float v = 0.f, cnt = 0.f;
        int bad = 0;
#pragma unroll 8
        for (int t = 0; t < T_STEPS; ++t) {
            float x = sf[u * PITCH + t];
            v = fmaf(0.95f, v, x);
            bad |= (fabsf(v - 1.0f) < GUARD);
            float s = (v > 1.0f) ? 1.0f : 0.0f;
            v *= (1.0f - s);
            cnt += s;
            if (WRITE_SPK)
                spk[(mBase + t) * 1024 + uglob] = __float2bfloat16(s);
        }
        mean_out[(size_t)b * 1024 + uglob] = cnt * (1.0f / 128.0f);
        if (bad) {
            unsigned int pos = atomicAdd(fixcnt, 1u);
            if (pos < FIXCAP) fixlist[pos] = (unsigned int)(b * 1024 + uglob);
        }
    }
}

// ============================================================================
// Exact recompute of flagged elements. One warp per element; lane owns
// timestep t = slot*32+lane, computes I via a PRIVATE ASCENDING-k fp32 FMA
// chain (bit-compatible with the R1-validated exact path). LIF via shuffle.
// KK = input width; WRITE_SPK = layer 1.
// ============================================================================
template <int KK, bool WRITE_SPK>
__global__ void __launch_bounds__(128)
fix_kernel(const __nv_bfloat16* __restrict__ Ain,  // (b*128+t, KK) bf16 inputs
           const float* __restrict__ Wf,           // (1024, KK) fp32 weights
           __nv_bfloat16* __restrict__ spk,        // layer-1 spike rewrite
           float* __restrict__ mean_out,
           const unsigned int* __restrict__ fixcnt,
           const unsigned int* __restrict__ fixlist)
{
    const unsigned int nfix = min(*fixcnt, FIXCAP);
    const int lane = threadIdx.x & 31;
    const int gw = (blockIdx.x * blockDim.x + threadIdx.x) >> 5;
    const int nw = (gridDim.x * blockDim.x) >> 5;

    for (unsigned int w = gw; w < nfix; w += nw) {
        const unsigned int idx = fixlist[w];
        const int b = idx >> 10, u = idx & 1023;
        const float* wr = Wf + (size_t)u * KK;   // lane-uniform -> broadcast

        float Iv[4];
#pragma unroll
        for (int slot = 0; slot < 4; ++slot) {
            const int t = slot * 32 + lane;
            const __nv_bfloat16* xr = Ain + ((size_t)b * T_STEPS + t) * KK;
            float a = 0.f;
            for (int kk = 0; kk < KK; kk += 8) {        // ascending k, in order
                uint4 raw = *(const uint4*)(xr + kk);   // 8 bf16
                float4 w0 = *(const float4*)(wr + kk);
                float4 w1 = *(const float4*)(wr + kk + 4);
                const __nv_bfloat162* px = (const __nv_bfloat162*)&raw;
                a = fmaf(__bfloat162float(px[0].x), w0.x, a);
                a = fmaf(__bfloat162float(px[0].y), w0.y, a);
                a = fmaf(__bfloat162float(px[1].x), w0.z, a);
                a = fmaf(__bfloat162float(px[1].y), w0.w, a);
                a = fmaf(__bfloat162float(px[2].x), w1.x, a);
                a = fmaf(__bfloat162float(px[2].y), w1.y, a);
                a = fmaf(__bfloat162float(px[3].x), w1.z, a);
                a = fmaf(__bfloat162float(px[3].y), w1.w, a);
            }
            Iv[slot] = a;
        }
        float v = 0.f, cnt = 0.f;
        for (int t = 0; t < T_STEPS; ++t) {
            float x = __shfl_sync(0xffffffffu, Iv[t >> 5], t & 31);
            v = fmaf(0.95f, v, x);
            float s = (v > 1.0f) ? 1.0f : 0.0f;
            v *= (1.0f - s);
            cnt += s;
            if (WRITE_SPK && lane == 0)
                spk[((size_t)b * T_STEPS + t) * 1024 + u] = __float2bfloat16(s);
        }
        if (lane == 0) mean_out[idx] = cnt * (1.0f / 128.0f);
    }
}

// ============================================================================
// prep kernels
// ============================================================================
__global__ void zero_cnt_kernel()
{
    if (threadIdx.x == 0) { g_fixcnt1 = 0; g_fixcnt2 = 0; }
}

// transpose (t,b) -> (b,t) rows while converting fp32 -> bf16 (binary: exact)
__global__ void __launch_bounds__(128)
f2bf_t_kernel(const float* __restrict__ x, __nv_bfloat16* __restrict__ y)
{
    const int row = blockIdx.x;            // t*BATCH + b
    const int t = row >> 9, b = row & 511;
    const float4* src = (const float4*)(x + (size_t)row * NLAB);
    __nv_bfloat16* dst = y + ((size_t)b * T_STEPS + t) * NLAB;
    float4 v = src[threadIdx.x];
    __nv_bfloat162 a; a.x = __float2bfloat16(v.x); a.y = __float2bfloat16(v.y);
    __nv_bfloat162 c; c.x = __float2bfloat16(v.z); c.y = __float2bfloat16(v.w);
    *(__nv_bfloat162*)(dst + threadIdx.x * 4)     = a;
    *(__nv_bfloat162*)(dst + threadIdx.x * 4 + 2) = c;
}

// 2-way bf16 split: hi = bf16(w), lo = bf16(w - hi); residual ~2^-18 |w|
__global__ void __launch_bounds__(256)
wsplit2_kernel(const float* __restrict__ w, __nv_bfloat16* __restrict__ o, int n)
{
    int i = blockIdx.x * blockDim.x + threadIdx.x;
    if (i >= n) return;
    float x = w[i];
    __nv_bfloat16 h = __float2bfloat16(x);
    float r1 = x - __bfloat162float(h);
    o[i] = h; o[n + i] = __float2bfloat16(r1);
}

// ---------------------------------------------------------------------------
extern "C" void kernel_launch(void* const* d_in, const int* in_sizes, int n_in,
                              void* d_out, int out_size)
{
    const float* spikes = (const float*)d_in[0];   // (T, B, NLAB) fp32
    const float* W1     = (const float*)d_in[1];   // (HID, NLAB)
    const float* W2     = (const float*)d_in[2];   // (SEM, HID)
    float* out = (float*)d_out;                    // [mean1 | mean2]

    __nv_bfloat16 *a1, *spk1, *ws1, *ws2;
    unsigned int *fc1, *fc2, *fl1, *fl2;
    cudaGetSymbolAddress((void**)&a1,   g_a1);
    cudaGetSymbolAddress((void**)&spk1, g_spk1);
    cudaGetSymbolAddress((void**)&ws1,  g_ws1);
    cudaGetSymbolAddress((void**)&ws2,  g_ws2);
    cudaGetSymbolAddress((void**)&fc1,  g_fixcnt1);
    cudaGetSymbolAddress((void**)&fc2,  g_fixcnt2);
    cudaGetSymbolAddress((void**)&fl1,  g_fixlist1);
    cudaGetSymbolAddress((void**)&fl2,  g_fixlist2);

    cudaFuncSetAttribute((const void*)gemm_lif<512, true>,
                         cudaFuncAttributeMaxDynamicSharedMemorySize, SMEM_BYTES);
    cudaFuncSetAttribute((const void*)gemm_lif<1024, false>,
                         cudaFuncAttributeMaxDynamicSharedMemorySize, SMEM_BYTES);

    // prep
    zero_cnt_kernel<<<1, 32>>>();
    f2bf_t_kernel<<<MROWS, 128>>>(spikes, a1);
    wsplit2_kernel<<<(HID * NLAB) / 256, 256>>>(W1, ws1, HID * NLAB);
    wsplit2_kernel<<<(SEM * HID) / 256, 256>>>(W2, ws2, SEM * HID);

    // layer 1: HMMA 2-split + fused guarded LIF, then exact-order fixup
    gemm_lif<512, true><<<dim3(HID / BN2, BATCH), 256, SMEM_BYTES>>>(
        a1, ws1, spk1, out, fc1, fl1);
    fix_kernel<512, true><<<1024, 128>>>(a1, W1, spk1, out, fc1, fl1);

    // layer 2: HMMA 2-split + fused guarded LIF, then exact-order fixup (mean only)
    gemm_lif<1024, false><<<dim3(SEM / BN2, BATCH), 256, SMEM_BYTES>>>(
        spk1, ws2, nullptr, out + (size_t)BATCH * HID, fc2, fl2);
    fix_kernel<1024, false><<<1024, 128>>>(spk1, W2, nullptr,
                                           out + (size_t)BATCH * HID, fc2, fl2);
}

// round 9
// speedup vs baseline: 2.0564x; 1.1136x over previous
#include <cuda_runtime.h>
#include <cuda_bf16.h>
#include <cstdint>

#define T_STEPS 128
#define BATCH   512
#define NLAB    512
#define HID     1024
#define SEM     1024
#define MROWS   (T_STEPS*BATCH)    // 65536
#define FIXCAP  (1u<<20)
#define GUARD   5e-5f

typedef unsigned long long ull;

// ---------------- scratch (device globals; no allocs allowed) ----------------
// M index is b*128 + t (batch-major): one 128-row GEMM tile = full time
// trajectory of one batch row -> LIF fuses into the epilogue.
__device__ __nv_bfloat16 g_a1  [(size_t)MROWS * NLAB];   //  64 MB spikes bf16 (b,t)-major
__device__ __nv_bfloat16 g_spk1[(size_t)MROWS * HID];    // 128 MB layer-1 spikes bf16
__device__ __nv_bfloat16 g_ws1 [2ull * HID * NLAB];      //   2 MB W1 2-splits
__device__ __nv_bfloat16 g_ws2 [2ull * SEM * HID];       //   4 MB W2 2-splits
__device__ unsigned int  g_fixcnt1, g_fixcnt2;
__device__ unsigned int  g_fixlist1[FIXCAP];
__device__ unsigned int  g_fixlist2[FIXCAP];

// ============================================================================
// HMMA 2-split GEMM, BM=128 x BN=256 tile, fused guarded LIF epilogue.
// Warp grid 2(m) x 4(n): each warp 64m x 64n.
// ============================================================================
#define BM2 128
#define BN2 256
#define BK2 32
#define STAGES 3
#define PADK  (BK2 + 8)
#define ROWB  (PADK * 2)               // 80 B/row
#define A_BYTES  (BM2 * ROWB)          // 10240
#define B_SPLIT  (BN2 * ROWB)          // 20480
#define STAGE_BYTES (A_BYTES + 2 * B_SPLIT)   // 51200
#define SMEM_BYTES  (STAGES * STAGE_BYTES)    // 153600 (>= LIF staging 132096)
#define PITCH 129

__device__ __forceinline__ uint32_t s2u(const void* p) {
    uint32_t a;
    asm("{ .reg .u64 t; cvta.to.shared.u64 t, %1; cvt.u32.u64 %0, t; }" : "=r"(a) : "l"(p));
    return a;
}
__device__ __forceinline__ void cpa16(uint32_t dst, const void* src) {
    asm volatile("cp.async.cg.shared.global [%0], [%1], 16;" :: "r"(dst), "l"(src) : "memory");
}
__device__ __forceinline__ void ldsm_x4(uint32_t* r, uint32_t addr) {
    asm volatile("ldmatrix.sync.aligned.m8n8.x4.shared.b16 {%0,%1,%2,%3}, [%4];"
                 : "=r"(r[0]), "=r"(r[1]), "=r"(r[2]), "=r"(r[3]) : "r"(addr));
}
__device__ __forceinline__ void mma16816(float* c, const uint32_t* a, uint32_t b0, uint32_t b1) {
    asm volatile("mma.sync.aligned.m16n8k16.row.col.f32.bf16.bf16.f32 "
                 "{%0,%1,%2,%3}, {%4,%5,%6,%7}, {%8,%9}, {%0,%1,%2,%3};"
                 : "+f"(c[0]), "+f"(c[1]), "+f"(c[2]), "+f"(c[3])
                 : "r"(a[0]), "r"(a[1]), "r"(a[2]), "r"(a[3]), "r"(b0), "r"(b1));
}

// A rows are (b*128+t); blockIdx.y = b. Epilogue: acc -> smem [u][t] -> LIF.
// Both layers guard-flag borderline elements; WRITE_SPK also emits bf16 spikes.
template <int K, bool WRITE_SPK>
__global__ void __launch_bounds__(256, 1)
gemm_lif(const __nv_bfloat16* __restrict__ A,
         const __nv_bfloat16* __restrict__ W,    // [2][1024][K]
         __nv_bfloat16* __restrict__ spk,        // WRITE_SPK only
         float* __restrict__ mean_out,
         unsigned int* __restrict__ fixcnt,
         unsigned int* __restrict__ fixlist)
{
    extern __shared__ char smem[];
    const uint32_t sb = s2u(smem);
    const int tid = threadIdx.x;
    const int b = blockIdx.y;
    const size_t mBase = (size_t)b * BM2;
    const size_t nBase = (size_t)blockIdx.x * BN2;
    constexpr int NC = K / BK2;

    auto load_stage = [&](int chunk, int stage) {
        const uint32_t s0 = sb + stage * STAGE_BYTES;
        const int k0 = chunk * BK2;
        // A: 128 rows x 4 chunks(16B) = 512, 2 per thread
#pragma unroll
        for (int j = 0; j < 2; ++j) {
            int c = tid * 2 + j;
            int row = c >> 2, kc = c & 3;
            cpa16(s0 + row * ROWB + kc * 16,
                  (const char*)(A + (mBase + row) * (size_t)K + k0) + kc * 16);
        }
        // B: 2 splits x 256 rows x 4 chunks = 2048, 8 per thread
#pragma unroll
        for (int j = 0; j < 8; ++j) {
            int c = tid + j * 256;
            int sp = c >> 10, rem = c & 1023;
            int row = rem >> 2, kc = rem & 3;
            cpa16(s0 + A_BYTES + sp * B_SPLIT + row * ROWB + kc * 16,
                  (const char*)(W + sp * (size_t)1024 * K + (nBase + row) * (size_t)K + k0) + kc * 16);
        }
        asm volatile("cp.async.commit_group;" ::: "memory");
    };

    const int wid  = tid >> 5, lane = tid & 31;
    const int wm = (wid >> 2) * 64;       // 0 / 64
    const int wn = (wid & 3) * 64;        // 0 / 64 / 128 / 192

    float acc[4][8][4];
#pragma unroll
    for (int mi = 0; mi < 4; ++mi)
#pragma unroll
        for (int ni = 0; ni < 8; ++ni)
#pragma unroll
            for (int q = 0; q < 4; ++q) acc[mi][ni][q] = 0.f;

#pragma unroll
    for (int s = 0; s < STAGES - 1; ++s) load_stage(s, s);

    const uint32_t a_lrow = (uint32_t)(lane & 15);
    const uint32_t a_koff = (uint32_t)(lane >> 4) * 8;
    const uint32_t b_lrow = (uint32_t)(((lane >> 3) & 1) * 8 + (lane & 7));
    const uint32_t b_koff = (uint32_t)(lane >> 4) * 8;

    int st = 0, nst = STAGES - 1;
    for (int i = 0; i < NC; ++i) {
        asm volatile("cp.async.wait_group %0;" :: "n"(STAGES - 2) : "memory");
        __syncthreads();
        const int nxt = i + STAGES - 1;
        if (nxt < NC) load_stage(nxt, nst);
        else asm volatile("cp.async.commit_group;" ::: "memory");
        if (++nst == STAGES) nst = 0;

        const uint32_t s0 = sb + st * STAGE_BYTES;
        if (++st == STAGES) st = 0;
#pragma unroll
        for (int ks = 0; ks < 2; ++ks) {
            const int k = ks * 16;
            uint32_t af[4][4];
#pragma unroll
            for (int mi = 0; mi < 4; ++mi)
                ldsm_x4(af[mi], s0 + (wm + mi * 16 + a_lrow) * ROWB + (k + a_koff) * 2);
#pragma unroll
            for (int sp = 0; sp < 2; ++sp) {
                const uint32_t bbase = s0 + A_BYTES + sp * B_SPLIT;
#pragma unroll
                for (int nb = 0; nb < 4; ++nb) {
                    uint32_t q[4];
                    ldsm_x4(q, bbase + (wn + nb * 16 + b_lrow) * ROWB + (k + b_koff) * 2);
#pragma unroll
                    for (int mi = 0; mi < 4; ++mi) {
                        mma16816(acc[mi][2 * nb],     af[mi], q[0], q[2]);
                        mma16816(acc[mi][2 * nb + 1], af[mi], q[1], q[3]);
                    }
                }
            }
        }
    }

    // ---- fused guarded LIF epilogue ----
    __syncthreads();                    // all compute + loads done; reuse smem
    float* sf = (float*)smem;           // [u][t], pitch PITCH (conflict-free)
    const int r0 = lane >> 2, c0 = (lane & 3) * 2;
#pragma unroll
    for (int mi = 0; mi < 4; ++mi)
#pragma unroll
        for (int ni = 0; ni < 8; ++ni) {
            const int t0 = wm + mi * 16 + r0;
            const int u0 = wn + ni * 8 + c0;
            sf[(u0    ) * PITCH + t0    ] = acc[mi][ni][0];
            sf[(u0 + 1) * PITCH + t0    ] = acc[mi][ni][1];
            sf[(u0    ) * PITCH + t0 + 8] = acc[mi][ni][2];
            sf[(u0 + 1) * PITCH + t0 + 8] = acc[mi][ni][3];
        }
    __syncthreads();

    {
        const int u = tid;              // all 256 threads, one unit each
        const size_t uglob = nBase + u;
        float v = 0.f, cnt = 0.f;
        int bad = 0;
#pragma unroll 8
        for (int t = 0; t < T_STEPS; ++t) {
            float x = sf[u * PITCH + t];
            v = fmaf(0.95f, v, x);
            bad |= (fabsf(v - 1.0f) < GUARD);
            float s = (v > 1.0f) ? 1.0f : 0.0f;
            v *= (1.0f - s);
            cnt += s;
            if (WRITE_SPK)
                spk[(mBase + t) * 1024 + uglob] = __float2bfloat16(s);
        }
        mean_out[(size_t)b * 1024 + uglob] = cnt * (1.0f / 128.0f);
        if (bad) {
            unsigned int pos = atomicAdd(fixcnt, 1u);
            if (pos < FIXCAP) fixlist[pos] = (unsigned int)(b * 1024 + uglob);
        }
    }
}

// ============================================================================
// Exact recompute of flagged elements. One warp per element; lane owns
// timestep t = slot*32+lane, computes I via a PRIVATE ASCENDING-k fp32 FMA
// chain (bit-compatible with the R1-validated exact path). LIF via shuffle.
// ============================================================================
template <int KK, bool WRITE_SPK>
__global__ void __launch_bounds__(128)
fix_kernel(const __nv_bfloat16* __restrict__ Ain,  // (b*128+t, KK) bf16 inputs
           const float* __restrict__ Wf,           // (1024, KK) fp32 weights
           __nv_bfloat16* __restrict__ spk,        // layer-1 spike rewrite
           float* __restrict__ mean_out,
           const unsigned int* __restrict__ fixcnt,
           const unsigned int* __restrict__ fixlist)
{
    const unsigned int nfix = min(*fixcnt, FIXCAP);
    const int lane = threadIdx.x & 31;
    const int gw = (blockIdx.x * blockDim.x + threadIdx.x) >> 5;
    const int nw = (gridDim.x * blockDim.x) >> 5;

    for (unsigned int w = gw; w < nfix; w += nw) {
        const unsigned int idx = fixlist[w];
        const int b = idx >> 10, u = idx & 1023;
        const float* wr = Wf + (size_t)u * KK;   // lane-uniform -> broadcast

        float Iv[4];
#pragma unroll
        for (int slot = 0; slot < 4; ++slot) {
            const int t = slot * 32 + lane;
            const __nv_bfloat16* xr = Ain + ((size_t)b * T_STEPS + t) * KK;
            float a = 0.f;
            for (int kk = 0; kk < KK; kk += 8) {        // ascending k, in order
                uint4 raw = *(const uint4*)(xr + kk);   // 8 bf16
                float4 w0 = *(const float4*)(wr + kk);
                float4 w1 = *(const float4*)(wr + kk + 4);
                const __nv_bfloat162* px = (const __nv_bfloat162*)&raw;
                a = fmaf(__bfloat162float(px[0].x), w0.x, a);
                a = fmaf(__bfloat162float(px[0].y), w0.y, a);
                a = fmaf(__bfloat162float(px[1].x), w0.z, a);
                a = fmaf(__bfloat162float(px[1].y), w0.w, a);
                a = fmaf(__bfloat162float(px[2].x), w1.x, a);
                a = fmaf(__bfloat162float(px[2].y), w1.y, a);
                a = fmaf(__bfloat162float(px[3].x), w1.z, a);
                a = fmaf(__bfloat162float(px[3].y), w1.w, a);
            }
            Iv[slot] = a;
        }
        float v = 0.f, cnt = 0.f;
        for (int t = 0; t < T_STEPS; ++t) {
            float x = __shfl_sync(0xffffffffu, Iv[t >> 5], t & 31);
            v = fmaf(0.95f, v, x);
            float s = (v > 1.0f) ? 1.0f : 0.0f;
            v *= (1.0f - s);
            cnt += s;
            if (WRITE_SPK && lane == 0)
                spk[((size_t)b * T_STEPS + t) * 1024 + u] = __float2bfloat16(s);
        }
        if (lane == 0) mean_out[idx] = cnt * (1.0f / 128.0f);
    }
}

// ============================================================================
// prep kernels
// ============================================================================
__global__ void zero_cnt_kernel()
{
    if (threadIdx.x == 0) { g_fixcnt1 = 0; g_fixcnt2 = 0; }
}

// transpose (t,b) -> (b,t) rows while converting fp32 -> bf16 (binary: exact)
__global__ void __launch_bounds__(128)
f2bf_t_kernel(const float* __restrict__ x, __nv_bfloat16* __restrict__ y)
{
    const int row = blockIdx.x;            // t*BATCH + b
    const int t = row >> 9, b = row & 511;
    const float4* src = (const float4*)(x + (size_t)row * NLAB);
    __nv_bfloat16* dst = y + ((size_t)b * T_STEPS + t) * NLAB;
    float4 v = src[threadIdx.x];
    __nv_bfloat162 a; a.x = __float2bfloat16(v.x); a.y = __float2bfloat16(v.y);
    __nv_bfloat162 c; c.x = __float2bfloat16(v.z); c.y = __float2bfloat16(v.w);
    *(__nv_bfloat162*)(dst + threadIdx.x * 4)     = a;
    *(__nv_bfloat162*)(dst + threadIdx.x * 4 + 2) = c;
}

// 2-way bf16 split: hi = bf16(w), lo = bf16(w - hi); residual ~2^-18 |w|
__global__ void __launch_bounds__(256)
wsplit2_kernel(const float* __restrict__ w, __nv_bfloat16* __restrict__ o, int n)
{
    int i = blockIdx.x * blockDim.x + threadIdx.x;
    if (i >= n) return;
    float x = w[i];
    __nv_bfloat16 h = __float2bfloat16(x);
    float r1 = x - __bfloat162float(h);
    o[i] = h; o[n + i] = __float2bfloat16(r1);
}

// ---------------------------------------------------------------------------
extern "C" void kernel_launch(void* const* d_in, const int* in_sizes, int n_in,
                              void* d_out, int out_size)
{
    const float* spikes = (const float*)d_in[0];   // (T, B, NLAB) fp32
    const float* W1     = (const float*)d_in[1];   // (HID, NLAB)
    const float* W2     = (const float*)d_in[2];   // (SEM, HID)
    float* out = (float*)d_out;                    // [mean1 | mean2]

    __nv_bfloat16 *a1, *spk1, *ws1, *ws2;
    unsigned int *fc1, *fc2, *fl1, *fl2;
    cudaGetSymbolAddress((void**)&a1,   g_a1);
    cudaGetSymbolAddress((void**)&spk1, g_spk1);
    cudaGetSymbolAddress((void**)&ws1,  g_ws1);
    cudaGetSymbolAddress((void**)&ws2,  g_ws2);
    cudaGetSymbolAddress((void**)&fc1,  g_fixcnt1);
    cudaGetSymbolAddress((void**)&fc2,  g_fixcnt2);
    cudaGetSymbolAddress((void**)&fl1,  g_fixlist1);
    cudaGetSymbolAddress((void**)&fl2,  g_fixlist2);

    cudaFuncSetAttribute((const void*)gemm_lif<512, true>,
                         cudaFuncAttributeMaxDynamicSharedMemorySize, SMEM_BYTES);
    cudaFuncSetAttribute((const void*)gemm_lif<1024, false>,
                         cudaFuncAttributeMaxDynamicSharedMemorySize, SMEM_BYTES);

    // prep
    zero_cnt_kernel<<<1, 32>>>();
    f2bf_t_kernel<<<MROWS, 128>>>(spikes, a1);
    wsplit2_kernel<<<(HID * NLAB) / 256, 256>>>(W1, ws1, HID * NLAB);
    wsplit2_kernel<<<(SEM * HID) / 256, 256>>>(W2, ws2, SEM * HID);

    // layer 1: HMMA 2-split + fused guarded LIF, then exact-order fixup
    gemm_lif<512, true><<<dim3(HID / BN2, BATCH), 256, SMEM_BYTES>>>(
        a1, ws1, spk1, out, fc1, fl1);
    fix_kernel<512, true><<<1024, 128>>>(a1, W1, spk1, out, fc1, fl1);

    // layer 2: HMMA 2-split + fused guarded LIF, then exact-order fixup (mean only)
    gemm_lif<1024, false><<<dim3(SEM / BN2, BATCH), 256, SMEM_BYTES>>>(
        spk1, ws2, nullptr, out + (size_t)BATCH * HID, fc2, fl2);
    fix_kernel<1024, false><<<1024, 128>>>(spk1, W2, nullptr,
                                           out + (size_t)BATCH * HID, fc2, fl2);
}

// round 10
// speedup vs baseline: 2.1032x; 1.0227x over previous
#include <cuda_runtime.h>
#include <cuda_bf16.h>
#include <cstdint>

#define T_STEPS 128
#define BATCH   512
#define NLAB    512
#define HID     1024
#define SEM     1024
#define MROWS   (T_STEPS*BATCH)    // 65536
#define FIXCAP  (1u<<20)
#define GUARD   5e-5f

typedef unsigned long long ull;

// ---------------- scratch (device globals; no allocs allowed) ----------------
// M index is b*128 + t (batch-major): one 128-row GEMM tile = full time
// trajectory of one batch row -> LIF fuses into the epilogue.
__device__ __nv_bfloat16 g_a1  [(size_t)MROWS * NLAB];   //  64 MB spikes bf16 (b,t)-major
__device__ __nv_bfloat16 g_spk1[(size_t)MROWS * HID];    // 128 MB layer-1 spikes bf16
__device__ __nv_bfloat16 g_ws1 [2ull * HID * NLAB];      //   2 MB W1 2-splits
__device__ __nv_bfloat16 g_ws2 [2ull * SEM * HID];       //   4 MB W2 2-splits
__device__ unsigned int  g_fixcnt1, g_fixcnt2;
__device__ unsigned int  g_fixlist1[FIXCAP];
__device__ unsigned int  g_fixlist2[FIXCAP];

// ============================================================================
// HMMA 2-split GEMM, BM=128 x BN=256 tile, 512 threads (16 warps, 4m x 4n),
// fused guarded LIF epilogue. Each warp: 32m x 64n.
// ============================================================================
#define BM2 128
#define BN2 256
#define BK2 32
#define NTHREADS 512
#define STAGES 3
#define PADK  (BK2 + 8)
#define ROWB  (PADK * 2)               // 80 B/row
#define A_BYTES  (BM2 * ROWB)          // 10240
#define B_SPLIT  (BN2 * ROWB)          // 20480
#define STAGE_BYTES (A_BYTES + 2 * B_SPLIT)   // 51200
#define SMEM_BYTES  (STAGES * STAGE_BYTES)    // 153600 (>= LIF staging 132096)
#define PITCH 129

__device__ __forceinline__ uint32_t s2u(const void* p) {
    uint32_t a;
    asm("{ .reg .u64 t; cvta.to.shared.u64 t, %1; cvt.u32.u64 %0, t; }" : "=r"(a) : "l"(p));
    return a;
}
__device__ __forceinline__ void cpa16(uint32_t dst, const void* src) {
    asm volatile("cp.async.cg.shared.global [%0], [%1], 16;" :: "r"(dst), "l"(src) : "memory");
}
__device__ __forceinline__ void ldsm_x4(uint32_t* r, uint32_t addr) {
    asm volatile("ldmatrix.sync.aligned.m8n8.x4.shared.b16 {%0,%1,%2,%3}, [%4];"
                 : "=r"(r[0]), "=r"(r[1]), "=r"(r[2]), "=r"(r[3]) : "r"(addr));
}
__device__ __forceinline__ void mma16816(float* c, const uint32_t* a, uint32_t b0, uint32_t b1) {
    asm volatile("mma.sync.aligned.m16n8k16.row.col.f32.bf16.bf16.f32 "
                 "{%0,%1,%2,%3}, {%4,%5,%6,%7}, {%8,%9}, {%0,%1,%2,%3};"
                 : "+f"(c[0]), "+f"(c[1]), "+f"(c[2]), "+f"(c[3])
                 : "r"(a[0]), "r"(a[1]), "r"(a[2]), "r"(a[3]), "r"(b0), "r"(b1));
}

// A rows are (b*128+t); blockIdx.y = b. Epilogue: acc -> smem [u][t] -> LIF.
// Both layers guard-flag borderline elements; WRITE_SPK also emits bf16 spikes.
template <int K, bool WRITE_SPK>
__global__ void __launch_bounds__(NTHREADS, 1)
gemm_lif(const __nv_bfloat16* __restrict__ A,
         const __nv_bfloat16* __restrict__ W,    // [2][1024][K]
         __nv_bfloat16* __restrict__ spk,        // WRITE_SPK only
         float* __restrict__ mean_out,
         unsigned int* __restrict__ fixcnt,
         unsigned int* __restrict__ fixlist)
{
    extern __shared__ char smem[];
    const uint32_t sb = s2u(smem);
    const int tid = threadIdx.x;
    const int b = blockIdx.y;
    const size_t mBase = (size_t)b * BM2;
    const size_t nBase = (size_t)blockIdx.x * BN2;
    constexpr int NC = K / BK2;

    auto load_stage = [&](int chunk, int stage) {
        const uint32_t s0 = sb + stage * STAGE_BYTES;
        const int k0 = chunk * BK2;
        // A: 128 rows x 4 chunks(16B) = 512, 1 per thread
        {
            int c = tid;
            int row = c >> 2, kc = c & 3;
            cpa16(s0 + row * ROWB + kc * 16,
                  (const char*)(A + (mBase + row) * (size_t)K + k0) + kc * 16);
        }
        // B: 2 splits x 256 rows x 4 chunks = 2048, 4 per thread
#pragma unroll
        for (int j = 0; j < 4; ++j) {
            int c = tid + j * NTHREADS;
            int sp = c >> 10, rem = c & 1023;
            int row = rem >> 2, kc = rem & 3;
            cpa16(s0 + A_BYTES + sp * B_SPLIT + row * ROWB + kc * 16,
                  (const char*)(W + sp * (size_t)1024 * K + (nBase + row) * (size_t)K + k0) + kc * 16);
        }
        asm volatile("cp.async.commit_group;" ::: "memory");
    };

    const int wid  = tid >> 5, lane = tid & 31;
    const int wm = (wid >> 2) * 32;       // 0/32/64/96
    const int wn = (wid & 3) * 64;        // 0/64/128/192

    float acc[2][8][4];
#pragma unroll
    for (int mi = 0; mi < 2; ++mi)
#pragma unroll
        for (int ni = 0; ni < 8; ++ni)
#pragma unroll
            for (int q = 0; q < 4; ++q) acc[mi][ni][q] = 0.f;

#pragma unroll
    for (int s = 0; s < STAGES - 1; ++s) load_stage(s, s);

    const uint32_t a_lrow = (uint32_t)(lane & 15);
    const uint32_t a_koff = (uint32_t)(lane >> 4) * 8;
    const uint32_t b_lrow = (uint32_t)(((lane >> 3) & 1) * 8 + (lane & 7));
    const uint32_t b_koff = (uint32_t)(lane >> 4) * 8;

    int st = 0, nst = STAGES - 1;
    for (int i = 0; i < NC; ++i) {
        asm volatile("cp.async.wait_group %0;" :: "n"(STAGES - 2) : "memory");
        __syncthreads();
        const int nxt = i + STAGES - 1;
        if (nxt < NC) load_stage(nxt, nst);
        else asm volatile("cp.async.commit_group;" ::: "memory");
        if (++nst == STAGES) nst = 0;

        const uint32_t s0 = sb + st * STAGE_BYTES;
        if (++st == STAGES) st = 0;
#pragma unroll
        for (int ks = 0; ks < 2; ++ks) {
            const int k = ks * 16;
            uint32_t af[2][4];
#pragma unroll
            for (int mi = 0; mi < 2; ++mi)
                ldsm_x4(af[mi], s0 + (wm + mi * 16 + a_lrow) * ROWB + (k + a_koff) * 2);
#pragma unroll
            for (int sp = 0; sp < 2; ++sp) {
                const uint32_t bbase = s0 + A_BYTES + sp * B_SPLIT;
#pragma unroll
                for (int nb = 0; nb < 4; ++nb) {
                    uint32_t q[4];
                    ldsm_x4(q, bbase + (wn + nb * 16 + b_lrow) * ROWB + (k + b_koff) * 2);
#pragma unroll
                    for (int mi = 0; mi < 2; ++mi) {
                        mma16816(acc[mi][2 * nb],     af[mi], q[0], q[2]);
                        mma16816(acc[mi][2 * nb + 1], af[mi], q[1], q[3]);
                    }
                }
            }
        }
    }

    // ---- fused guarded LIF epilogue ----
    __syncthreads();                    // all compute + loads done; reuse smem
    float* sf = (float*)smem;           // [u][t], pitch PITCH (conflict-free)
    const int r0 = lane >> 2, c0 = (lane & 3) * 2;
#pragma unroll
    for (int mi = 0; mi < 2; ++mi)
#pragma unroll
        for (int ni = 0; ni < 8; ++ni) {
            const int t0 = wm + mi * 16 + r0;
            const int u0 = wn + ni * 8 + c0;
            sf[(u0    ) * PITCH + t0    ] = acc[mi][ni][0];
            sf[(u0 + 1) * PITCH + t0    ] = acc[mi][ni][1];
            sf[(u0    ) * PITCH + t0 + 8] = acc[mi][ni][2];
            sf[(u0 + 1) * PITCH + t0 + 8] = acc[mi][ni][3];
        }
    __syncthreads();

    if (tid < BN2) {
        const int u = tid;              // one unit per thread
        const size_t uglob = nBase + u;
        float v = 0.f, cnt = 0.f;
        int bad = 0;
#pragma unroll 8
        for (int t = 0; t < T_STEPS; ++t) {
            float x = sf[u * PITCH + t];
            v = fmaf(0.95f, v, x);
            bad |= (fabsf(v - 1.0f) < GUARD);
            float s = (v > 1.0f) ? 1.0f : 0.0f;
            v *= (1.0f - s);
            cnt += s;
            if (WRITE_SPK)
                spk[(mBase + t) * 1024 + uglob] = __float2bfloat16(s);
        }
        mean_out[(size_t)b * 1024 + uglob] = cnt * (1.0f / 128.0f);
        if (bad) {
            unsigned int pos = atomicAdd(fixcnt, 1u);
            if (pos < FIXCAP) fixlist[pos] = (unsigned int)(b * 1024 + uglob);
        }
    }
}

// ============================================================================
// Exact recompute of flagged elements. One warp per element; lane owns
// timestep t = slot*32+lane, computes I via a PRIVATE ASCENDING-k fp32 FMA
// chain (bit-compatible with the R1-validated exact path). LIF via shuffle.
// ============================================================================
template <int KK, bool WRITE_SPK>
__global__ void __launch_bounds__(128)
fix_kernel(const __nv_bfloat16* __restrict__ Ain,  // (b*128+t, KK) bf16 inputs
           const float* __restrict__ Wf,           // (1024, KK) fp32 weights
           __nv_bfloat16* __restrict__ spk,        // layer-1 spike rewrite
           float* __restrict__ mean_out,
           const unsigned int* __restrict__ fixcnt,
           const unsigned int* __restrict__ fixlist)
{
    const unsigned int nfix = min(*fixcnt, FIXCAP);
    const int lane = threadIdx.x & 31;
    const int gw = (blockIdx.x * blockDim.x + threadIdx.x) >> 5;
    const int nw = (gridDim.x * blockDim.x) >> 5;

    for (unsigned int w = gw; w < nfix; w += nw) {
        const unsigned int idx = fixlist[w];
        const int b = idx >> 10, u = idx & 1023;
        const float* wr = Wf + (size_t)u * KK;   // lane-uniform -> broadcast

        float Iv[4];
#pragma unroll
        for (int slot = 0; slot < 4; ++slot) {
            const int t = slot * 32 + lane;
            const __nv_bfloat16* xr = Ain + ((size_t)b * T_STEPS + t) * KK;
            float a = 0.f;
            for (int kk = 0; kk < KK; kk += 8) {        // ascending k, in order
                uint4 raw = *(const uint4*)(xr + kk);   // 8 bf16
                float4 w0 = *(const float4*)(wr + kk);
                float4 w1 = *(const float4*)(wr + kk + 4);
                const __nv_bfloat162* px = (const __nv_bfloat162*)&raw;
                a = fmaf(__bfloat162float(px[0].x), w0.x, a);
                a = fmaf(__bfloat162float(px[0].y), w0.y, a);
                a = fmaf(__bfloat162float(px[1].x), w0.z, a);
                a = fmaf(__bfloat162float(px[1].y), w0.w, a);
                a = fmaf(__bfloat162float(px[2].x), w1.x, a);
                a = fmaf(__bfloat162float(px[2].y), w1.y, a);
                a = fmaf(__bfloat162float(px[3].x), w1.z, a);
                a = fmaf(__bfloat162float(px[3].y), w1.w, a);
            }
            Iv[slot] = a;
        }
        float v = 0.f, cnt = 0.f;
        for (int t = 0; t < T_STEPS; ++t) {
            float x = __shfl_sync(0xffffffffu, Iv[t >> 5], t & 31);
            v = fmaf(0.95f, v, x);
            float s = (v > 1.0f) ? 1.0f : 0.0f;
            v *= (1.0f - s);
            cnt += s;
            if (WRITE_SPK && lane == 0)
                spk[((size_t)b * T_STEPS + t) * 1024 + u] = __float2bfloat16(s);
        }
        if (lane == 0) mean_out[idx] = cnt * (1.0f / 128.0f);
    }
}

// ============================================================================
// prep kernels
// ============================================================================
__global__ void zero_cnt_kernel()
{
    if (threadIdx.x == 0) { g_fixcnt1 = 0; g_fixcnt2 = 0; }
}

// transpose (t,b) -> (b,t) rows while converting fp32 -> bf16 (binary: exact)
__global__ void __launch_bounds__(128)
f2bf_t_kernel(const float* __restrict__ x, __nv_bfloat16* __restrict__ y)
{
    const int row = blockIdx.x;            // t*BATCH + b
    const int t = row >> 9, b = row & 511;
    const float4* src = (const float4*)(x + (size_t)row * NLAB);
    __nv_bfloat16* dst = y + ((size_t)b * T_STEPS + t) * NLAB;
    float4 v = src[threadIdx.x];
    __nv_bfloat162 a; a.x = __float2bfloat16(v.x); a.y = __float2bfloat16(v.y);
    __nv_bfloat162 c; c.x = __float2bfloat16(v.z); c.y = __float2bfloat16(v.w);
    *(__nv_bfloat162*)(dst + threadIdx.x * 4)     = a;
    *(__nv_bfloat162*)(dst + threadIdx.x * 4 + 2) = c;
}

// 2-way bf16 split: hi = bf16(w), lo = bf16(w - hi); residual ~2^-18 |w|
__global__ void __launch_bounds__(256)
wsplit2_kernel(const float* __restrict__ w, __nv_bfloat16* __restrict__ o, int n)
{
    int i = blockIdx.x * blockDim.x + threadIdx.x;
    if (i >= n) return;
    float x = w[i];
    __nv_bfloat16 h = __float2bfloat16(x);
    float r1 = x - __bfloat162float(h);
    o[i] = h; o[n + i] = __float2bfloat16(r1);
}

// ---------------------------------------------------------------------------
extern "C" void kernel_launch(void* const* d_in, const int* in_sizes, int n_in,
                              void* d_out, int out_size)
{
    const float* spikes = (const float*)d_in[0];   // (T, B, NLAB) fp32
    const float* W1     = (const float*)d_in[1];   // (HID, NLAB)
    const float* W2     = (const float*)d_in[2];   // (SEM, HID)
    float* out = (float*)d_out;                    // [mean1 | mean2]

    __nv_bfloat16 *a1, *spk1, *ws1, *ws2;
    unsigned int *fc1, *fc2, *fl1, *fl2;
    cudaGetSymbolAddress((void**)&a1,   g_a1);
    cudaGetSymbolAddress((void**)&spk1, g_spk1);
    cudaGetSymbolAddress((void**)&ws1,  g_ws1);
    cudaGetSymbolAddress((void**)&ws2,  g_ws2);
    cudaGetSymbolAddress((void**)&fc1,  g_fixcnt1);
    cudaGetSymbolAddress((void**)&fc2,  g_fixcnt2);
    cudaGetSymbolAddress((void**)&fl1,  g_fixlist1);
    cudaGetSymbolAddress((void**)&fl2,  g_fixlist2);

    cudaFuncSetAttribute((const void*)gemm_lif<512, true>,
                         cudaFuncAttributeMaxDynamicSharedMemorySize, SMEM_BYTES);
    cudaFuncSetAttribute((const void*)gemm_lif<1024, false>,
                         cudaFuncAttributeMaxDynamicSharedMemorySize, SMEM_BYTES);

    // prep
    zero_cnt_kernel<<<1, 32>>>();
    f2bf_t_kernel<<<MROWS, 128>>>(spikes, a1);
    wsplit2_kernel<<<(HID * NLAB) / 256, 256>>>(W1, ws1, HID * NLAB);
    wsplit2_kernel<<<(SEM * HID) / 256, 256>>>(W2, ws2, SEM * HID);

    // layer 1: HMMA 2-split + fused guarded LIF, then exact-order fixup
    gemm_lif<512, true><<<dim3(HID / BN2, BATCH), NTHREADS, SMEM_BYTES>>>(
        a1, ws1, spk1, out, fc1, fl1);
    fix_kernel<512, true><<<1024, 128>>>(a1, W1, spk1, out, fc1, fl1);

    // layer 2: HMMA 2-split + fused guarded LIF, then exact-order fixup (mean only)
    gemm_lif<1024, false><<<dim3(SEM / BN2, BATCH), NTHREADS, SMEM_BYTES>>>(
        spk1, ws2, nullptr, out + (size_t)BATCH * HID, fc2, fl2);
    fix_kernel<1024, false><<<1024, 128>>>(spk1, W2, nullptr,
                                           out + (size_t)BATCH * HID, fc2, fl2);
}